// round 1
// baseline (speedup 1.0000x reference)
#include <cuda_runtime.h>
#include <cstdint>

#define BB 1024
#define TT 256
#define EE 384
#define HH 64

// Scratch for q, k, v projections (67 MB each). Static __device__ arrays per
// the no-allocation rule.
__device__ float g_q[BB * TT * HH];
__device__ float g_k[BB * TT * HH];
__device__ float g_v[BB * TT * HH];

// ---- packed f32x2 helpers (Blackwell FFMA2: 2x fp32 throughput) ----
__device__ __forceinline__ unsigned long long pk2(float lo, float hi) {
    unsigned long long r;
    asm("mov.b64 %0, {%1, %2};" : "=l"(r) : "f"(lo), "f"(hi));
    return r;
}
__device__ __forceinline__ float2 upk2(unsigned long long v) {
    float2 r;
    asm("mov.b64 {%0, %1}, %2;" : "=f"(r.x), "=f"(r.y) : "l"(v));
    return r;
}
__device__ __forceinline__ void fma2(unsigned long long& d, unsigned long long a, unsigned long long b) {
    asm("fma.rn.f32x2 %0, %1, %2, %3;" : "=l"(d) : "l"(a), "l"(b), "l"(d));
}
__device__ __forceinline__ unsigned long long mul2(unsigned long long a, unsigned long long b) {
    unsigned long long d;
    asm("mul.rn.f32x2 %0, %1, %2;" : "=l"(d) : "l"(a), "l"(b));
    return d;
}
__device__ __forceinline__ float ex2f(float x) {
    float y;
    asm("ex2.approx.ftz.f32 %0, %1;" : "=f"(y) : "f"(x));
    return y;
}

// ============================================================================
// Kernel 1: fused QKV projection.
// Treat x as [B*T, 384] row-major; W* are [384, 64].
// Grid: (B*T)/64 CTAs of 256 threads. Each CTA computes a 64x64 output tile
// for q, k, v simultaneously (x tile loaded once for all three).
// Thread (tx, ty): rows r0 + ty*4 + {0..3}, cols tx*4 + {0..3}.
// ============================================================================
__global__ void __launch_bounds__(256) qkv_kernel(
    const float* __restrict__ x, const float* __restrict__ Wq,
    const float* __restrict__ Wk, const float* __restrict__ Wv)
{
    __shared__ __align__(16) float xs[32][68];       // [k][row], padded
    __shared__ __align__(16) float ws[3][32][64];    // [mat][k][col]

    int tid = threadIdx.x;
    int tx = tid & 15, ty = tid >> 4;
    long long r0 = (long long)blockIdx.x * 64;

    unsigned long long aq[4][2], ak[4][2], av[4][2];
#pragma unroll
    for (int i = 0; i < 4; i++)
#pragma unroll
        for (int j = 0; j < 2; j++) { aq[i][j] = 0ull; ak[i][j] = 0ull; av[i][j] = 0ull; }

    for (int k0 = 0; k0 < EE; k0 += 32) {
        __syncthreads();
        // load x tile: 64 rows x 32 k, transposed into xs[k][row]
#pragma unroll
        for (int i = 0; i < 2; i++) {
            int idx = tid + i * 256;             // 0..511 float4s
            int r = idx >> 3;                    // 8 float4 per row
            int c = (idx & 7) << 2;
            float4 v4 = *(const float4*)(x + (r0 + r) * EE + k0 + c);
            xs[c + 0][r] = v4.x; xs[c + 1][r] = v4.y;
            xs[c + 2][r] = v4.z; xs[c + 3][r] = v4.w;
        }
        // load W tiles: 32 k x 64 cols each
#pragma unroll
        for (int i = 0; i < 2; i++) {
            int idx = tid + i * 256;             // 0..511 float4s
            int kr = idx >> 4;                   // 16 float4 per row
            int c = (idx & 15) << 2;
            *(float4*)&ws[0][kr][c] = *(const float4*)(Wq + (k0 + kr) * HH + c);
            *(float4*)&ws[1][kr][c] = *(const float4*)(Wk + (k0 + kr) * HH + c);
            *(float4*)&ws[2][kr][c] = *(const float4*)(Wv + (k0 + kr) * HH + c);
        }
        __syncthreads();
#pragma unroll
        for (int kk = 0; kk < 32; kk++) {
            float4 xv = *(const float4*)&xs[kk][ty << 2];
            unsigned long long xa[4] = { pk2(xv.x, xv.x), pk2(xv.y, xv.y),
                                         pk2(xv.z, xv.z), pk2(xv.w, xv.w) };
            float4 wq4 = *(const float4*)&ws[0][kk][tx << 2];
            float4 wk4 = *(const float4*)&ws[1][kk][tx << 2];
            float4 wv4 = *(const float4*)&ws[2][kk][tx << 2];
            unsigned long long q0 = pk2(wq4.x, wq4.y), q1 = pk2(wq4.z, wq4.w);
            unsigned long long k0p = pk2(wk4.x, wk4.y), k1p = pk2(wk4.z, wk4.w);
            unsigned long long v0 = pk2(wv4.x, wv4.y), v1 = pk2(wv4.z, wv4.w);
#pragma unroll
            for (int i = 0; i < 4; i++) {
                fma2(aq[i][0], xa[i], q0);  fma2(aq[i][1], xa[i], q1);
                fma2(ak[i][0], xa[i], k0p); fma2(ak[i][1], xa[i], k1p);
                fma2(av[i][0], xa[i], v0);  fma2(av[i][1], xa[i], v1);
            }
        }
    }
#pragma unroll
    for (int i = 0; i < 4; i++) {
        long long R = r0 + (ty << 2) + i;
        float2 a0 = upk2(aq[i][0]), a1 = upk2(aq[i][1]);
        *(float4*)(g_q + R * HH + (tx << 2)) = make_float4(a0.x, a0.y, a1.x, a1.y);
        a0 = upk2(ak[i][0]); a1 = upk2(ak[i][1]);
        *(float4*)(g_k + R * HH + (tx << 2)) = make_float4(a0.x, a0.y, a1.x, a1.y);
        a0 = upk2(av[i][0]); a1 = upk2(av[i][1]);
        *(float4*)(g_v + R * HH + (tx << 2)) = make_float4(a0.x, a0.y, a1.x, a1.y);
    }
}

// ============================================================================
// Kernel 2: causal attention, 1 CTA per batch, 256 threads (1 per query row).
// K/V tiles in smem (128 KB). Online softmax in chunks of 16 keys, all math
// in f32x2, exp via ex2.approx (scale*log2e folded into q).
// Warp w handles row block (w<4 ? w : 11-w)*32 so each SMSP gets a balanced
// (low, high) causal-triangle pair.
// ============================================================================
__global__ void __launch_bounds__(256, 1) attn_kernel(float* __restrict__ out)
{
    extern __shared__ __align__(16) float sm[];
    float* ks = sm;                 // [256][64]
    float* vs = sm + TT * HH;       // [256][64]

    int b = blockIdx.x;
    int tid = threadIdx.x;

    const float4* kb = (const float4*)(g_k + (size_t)b * TT * HH);
    const float4* vb = (const float4*)(g_v + (size_t)b * TT * HH);
    float4* ks4 = (float4*)ks;
    float4* vs4 = (float4*)vs;
#pragma unroll 4
    for (int i = tid; i < TT * HH / 4; i += 256) { ks4[i] = kb[i]; vs4[i] = vb[i]; }

    int w = tid >> 5, lane = tid & 31;
    int blk = (w < 4) ? w : (11 - w);
    int row = blk * 32 + lane;

    const float sc = 0.125f * 1.44269504089f;   // 1/sqrt(64) * log2(e)
    unsigned long long qv[32];
    const float4* qp = (const float4*)(g_q + ((size_t)b * TT + row) * HH);
#pragma unroll
    for (int i = 0; i < 16; i++) {
        float4 t = qp[i];
        qv[2 * i]     = pk2(t.x * sc, t.y * sc);
        qv[2 * i + 1] = pk2(t.z * sc, t.w * sc);
    }

    unsigned long long acc[32];
#pragma unroll
    for (int i = 0; i < 32; i++) acc[i] = 0ull;
    float m = -INFINITY, l = 0.f;

    __syncthreads();

    for (int jc = 0; jc <= row; jc += 16) {
        int rem = row - jc;
        float s[16];
        float cmax = -INFINITY;
#pragma unroll
        for (int jj = 0; jj < 16; jj++) {
            if (jj <= rem) {
                const float4* kr = (const float4*)(ks + (jc + jj) * HH);
                unsigned long long d2 = 0ull;
#pragma unroll
                for (int i = 0; i < 16; i++) {
                    float4 kv4 = kr[i];
                    fma2(d2, qv[2 * i],     pk2(kv4.x, kv4.y));
                    fma2(d2, qv[2 * i + 1], pk2(kv4.z, kv4.w));
                }
                float2 dd = upk2(d2);
                float d = dd.x + dd.y;
                s[jj] = d;
                cmax = fmaxf(cmax, d);
            } else {
                s[jj] = -INFINITY;
            }
        }
        float mnew = fmaxf(m, cmax);
        float corr = ex2f(m - mnew);    // ftz: 2^-inf -> 0 on first chunk
        m = mnew;
        l *= corr;
        unsigned long long c2 = pk2(corr, corr);
#pragma unroll
        for (int i = 0; i < 32; i++) acc[i] = mul2(acc[i], c2);
#pragma unroll
        for (int jj = 0; jj < 16; jj++) {
            if (jj <= rem) {
                float p = ex2f(s[jj] - m);
                l += p;
                unsigned long long p2 = pk2(p, p);
                const float4* vr = (const float4*)(vs + (jc + jj) * HH);
#pragma unroll
                for (int i = 0; i < 16; i++) {
                    float4 vv = vr[i];
                    fma2(acc[2 * i],     p2, pk2(vv.x, vv.y));
                    fma2(acc[2 * i + 1], p2, pk2(vv.z, vv.w));
                }
            }
        }
    }

    float inv = 1.0f / l;
    unsigned long long i2 = pk2(inv, inv);

    // Stage through smem (padded stride 17 float4/row) to avoid bank conflicts
    // and make the final global store fully coalesced. Reuses ks (safe after
    // the barrier: all threads are past their k/v reads).
    __syncthreads();
    float4* s4 = (float4*)ks;
#pragma unroll
    for (int i = 0; i < 16; i++) {
        float2 a0 = upk2(mul2(acc[2 * i], i2));
        float2 a1 = upk2(mul2(acc[2 * i + 1], i2));
        s4[row * 17 + i] = make_float4(a0.x, a0.y, a1.x, a1.y);
    }
    __syncthreads();
    float4* ob = (float4*)(out + (size_t)b * TT * HH);
#pragma unroll 4
    for (int g = tid; g < TT * HH / 4; g += 256) {
        ob[g] = s4[(g >> 4) * 17 + (g & 15)];
    }
}

extern "C" void kernel_launch(void* const* d_in, const int* in_sizes, int n_in,
                              void* d_out, int out_size)
{
    (void)in_sizes; (void)n_in; (void)out_size;
    const float* x  = (const float*)d_in[0];
    const float* Wq = (const float*)d_in[1];
    const float* Wk = (const float*)d_in[2];
    const float* Wv = (const float*)d_in[3];
    float* out = (float*)d_out;

    cudaFuncSetAttribute(attn_kernel, cudaFuncAttributeMaxDynamicSharedMemorySize,
                         2 * TT * HH * (int)sizeof(float));

    qkv_kernel<<<(BB * TT) / 64, 256>>>(x, Wq, Wk, Wv);
    attn_kernel<<<BB, 256, 2 * TT * HH * sizeof(float)>>>(out);
}

// round 4
// speedup vs baseline: 2.0406x; 2.0406x over previous
#include <cuda_runtime.h>
#include <cstdint>

#define BB 1024
#define TT 256
#define EE 384
#define HH 64

// Scratch (no-allocation rule: __device__ globals).
__device__ float g_q[BB * TT * HH];
__device__ float g_k[BB * TT * HH];
__device__ float g_v[BB * TT * HH];
// W fused+transposed+k-permuted+tf32-rounded: [mat][n][k_perm], row = m*64+n.
__device__ float g_wt[3 * HH * EE];

// ---------------------------------------------------------------------------
// helpers
// ---------------------------------------------------------------------------
__device__ __forceinline__ unsigned long long pk2(float lo, float hi) {
    unsigned long long r;
    asm("mov.b64 %0, {%1, %2};" : "=l"(r) : "f"(lo), "f"(hi));
    return r;
}
__device__ __forceinline__ float2 upk2(unsigned long long v) {
    float2 r;
    asm("mov.b64 {%0, %1}, %2;" : "=f"(r.x), "=f"(r.y) : "l"(v));
    return r;
}
__device__ __forceinline__ void fma2(unsigned long long& d, unsigned long long a, unsigned long long b) {
    asm("fma.rn.f32x2 %0, %1, %2, %3;" : "=l"(d) : "l"(a), "l"(b), "l"(d));
}
__device__ __forceinline__ unsigned long long mul2(unsigned long long a, unsigned long long b) {
    unsigned long long d;
    asm("mul.rn.f32x2 %0, %1, %2;" : "=l"(d) : "l"(a), "l"(b));
    return d;
}
__device__ __forceinline__ float ex2f(float x) {
    float y;
    asm("ex2.approx.ftz.f32 %0, %1;" : "=f"(y) : "f"(x));
    return y;
}
__device__ __forceinline__ uint32_t tf32r(float f) {
    uint32_t r;
    asm("cvt.rna.tf32.f32 %0, %1;" : "=r"(r) : "f"(f));
    return r;
}
// m16n8k8 tf32 mma (baseline PTX, works on compute_103).
__device__ __forceinline__ void mma8(float* d, const uint32_t* a, uint32_t b0, uint32_t b1) {
    asm("mma.sync.aligned.m16n8k8.row.col.f32.tf32.tf32.f32 "
        "{%0,%1,%2,%3}, {%4,%5,%6,%7}, {%8,%9}, {%0,%1,%2,%3};"
        : "+f"(d[0]), "+f"(d[1]), "+f"(d[2]), "+f"(d[3])
        : "r"(a[0]), "r"(a[1]), "r"(a[2]), "r"(a[3]), "r"(b0), "r"(b1));
}
__device__ __forceinline__ void cpa16(uint32_t dst, const void* src) {
    asm volatile("cp.async.cg.shared.global [%0], [%1], 16;" :: "r"(dst), "l"(src));
}
__device__ __forceinline__ uint32_t smem_u32(const void* p) {
    uint32_t a;
    asm("{ .reg .u64 t; cvta.to.shared.u64 t, %1; cvt.u32.u64 %0, t; }" : "=r"(a) : "l"(p));
    return a;
}

// ---------------------------------------------------------------------------
// Kernel 0: build g_wt. Row = m*64+n, col kp; within each 8-group, position p
// holds source k = base + (p>>1) + ((p&1)<<2) so the B fragment (b0 at k=c,
// b1 at k=c+4) is one aligned 8-byte LDS.64. Values tf32-rounded (rna).
// ---------------------------------------------------------------------------
__global__ void wt_kernel(const float* __restrict__ Wq, const float* __restrict__ Wk,
                          const float* __restrict__ Wv) {
    int idx = blockIdx.x * 256 + threadIdx.x;
    if (idx >= 3 * HH * EE) return;
    int m  = idx / (HH * EE);
    int n  = (idx / EE) & 63;
    int kp = idx % EE;
    int k  = (kp & ~7) + ((kp & 7) >> 1) + ((kp & 1) << 2);
    const float* W = (m == 0) ? Wq : (m == 1) ? Wk : Wv;
    uint32_t v = tf32r(W[k * HH + n]);
    g_wt[idx] = __uint_as_float(v);
}

// ---------------------------------------------------------------------------
// Kernel 1: QKV projection with mma.sync tf32.
// CTA: 128 rows x 192 cols (q|k|v). 8 warps as 4(M) x 2(N): warp = 32 x 96.
// K in 12 chunks of 32, double-buffered cp.async.
// smem per stage: xs [128][40] f32 (XOR-swizzled k), ws [192][40] f32.
// ---------------------------------------------------------------------------
#define QS_STAGE 51200
#define QS_WOFF  20480

__device__ __forceinline__ void qkv_load(uint32_t sbase, int stage, int chunk,
                                         const float* __restrict__ x, long long r0) {
    uint32_t xs = sbase + stage * QS_STAGE;
    uint32_t ws = xs + QS_WOFF;
    int tid = threadIdx.x;
#pragma unroll
    for (int i = 0; i < 4; i++) {                 // x: 128 rows x 32 f = 1024x16B
        int idx = tid + i * 256;
        int row = idx >> 3, c16 = idx & 7;
        uint32_t doff = (uint32_t)(c16 * 16) ^ (uint32_t)((row & 4) << 2);
        cpa16(xs + row * 160 + doff, x + (r0 + row) * EE + chunk * 32 + c16 * 4);
    }
#pragma unroll
    for (int i = 0; i < 6; i++) {                 // W: 192 rows x 32 f = 1536x16B
        int idx = tid + i * 256;
        int row = idx >> 3, c16 = idx & 7;
        cpa16(ws + row * 160 + c16 * 16, g_wt + row * EE + chunk * 32 + c16 * 4);
    }
}

__global__ void __launch_bounds__(256, 1) qkv_kernel(const float* __restrict__ x)
{
    extern __shared__ __align__(16) char smem[];
    uint32_t sbase = smem_u32(smem);
    int tid = threadIdx.x, wid = tid >> 5, lane = tid & 31;
    int g = lane >> 2, tig = lane & 3;
    int wm = wid >> 1, nh = wid & 1;
    int rb = wm * 32;
    long long r0 = (long long)blockIdx.x * 128;

    float acc[12][2][4];
#pragma unroll
    for (int nt = 0; nt < 12; nt++)
#pragma unroll
        for (int mt = 0; mt < 2; mt++)
#pragma unroll
            for (int i = 0; i < 4; i++) acc[nt][mt][i] = 0.f;

    qkv_load(sbase, 0, 0, x, r0);
    asm volatile("cp.async.commit_group;" ::: "memory");
    qkv_load(sbase, 1, 1, x, r0);
    asm volatile("cp.async.commit_group;" ::: "memory");

    for (int c = 0; c < 12; c++) {
        if (c < 11) asm volatile("cp.async.wait_group 1;" ::: "memory");
        else        asm volatile("cp.async.wait_group 0;" ::: "memory");
        __syncthreads();

        const float* xs = (const float*)(smem + (c & 1) * QS_STAGE);
        const float* ws = (const float*)(smem + (c & 1) * QS_STAGE + QS_WOFF);
#pragma unroll
        for (int ks = 0; ks < 4; ks++) {
            int kb = ks * 8;
            uint32_t A[2][4];
#pragma unroll
            for (int mt = 0; mt < 2; mt++) {
                int r_ = rb + mt * 16 + g;
                int sw = r_ & 4;                 // XOR swizzle bit
                A[mt][0] = tf32r(xs[r_ * 40 + ((kb + tig) ^ sw)]);
                A[mt][1] = tf32r(xs[(r_ + 8) * 40 + ((kb + tig) ^ sw)]);
                A[mt][2] = tf32r(xs[r_ * 40 + ((kb + tig + 4) ^ sw)]);
                A[mt][3] = tf32r(xs[(r_ + 8) * 40 + ((kb + tig + 4) ^ sw)]);
            }
#pragma unroll
            for (int nt = 0; nt < 12; nt++) {
                int brow = nh * 96 + nt * 8 + g;
                float2 bv = *(const float2*)&ws[brow * 40 + kb + 2 * tig];
                uint32_t b0 = __float_as_uint(bv.x), b1 = __float_as_uint(bv.y);
                mma8(acc[nt][0], A[0], b0, b1);
                mma8(acc[nt][1], A[1], b0, b1);
            }
        }
        __syncthreads();

        if (c + 2 < 12) {
            qkv_load(sbase, c & 1, c + 2, x, r0);
            asm volatile("cp.async.commit_group;" ::: "memory");
        }
    }

    // epilogue: c0/c1 -> (row, 2tig/2tig+1), c2/c3 -> (row+8, ...)
    float* const outs[3] = { g_q, g_k, g_v };
#pragma unroll
    for (int nt = 0; nt < 12; nt++) {
        int gc = nh * 96 + nt * 8;
        float* op = outs[gc >> 6] + (gc & 63) + 2 * tig;
#pragma unroll
        for (int mt = 0; mt < 2; mt++) {
            long long row0 = r0 + rb + mt * 16 + g;
            *(float2*)(op + row0 * HH) = make_float2(acc[nt][mt][0], acc[nt][mt][1]);
            *(float2*)(op + (row0 + 8) * HH) = make_float2(acc[nt][mt][2], acc[nt][mt][3]);
        }
    }
}

// ---------------------------------------------------------------------------
// Kernel 2: causal attention. 1 CTA/batch, 256 threads (1 per query row).
// FFMA2 math; QK dot uses 4 independent accumulator chains (ILP 4); masked
// keys via s=-inf -> ex2->0 (branchless).
// ---------------------------------------------------------------------------
__global__ void __launch_bounds__(256, 1) attn_kernel(float* __restrict__ out)
{
    extern __shared__ __align__(16) float sm[];
    float* ks = sm;                 // [256][64]
    float* vs = sm + TT * HH;       // [256][64]

    int b = blockIdx.x;
    int tid = threadIdx.x;

    const float4* kb = (const float4*)(g_k + (size_t)b * TT * HH);
    const float4* vb = (const float4*)(g_v + (size_t)b * TT * HH);
    float4* ks4 = (float4*)ks;
    float4* vs4 = (float4*)vs;
#pragma unroll 4
    for (int i = tid; i < TT * HH / 4; i += 256) { ks4[i] = kb[i]; vs4[i] = vb[i]; }

    int w = tid >> 5, lane = tid & 31;
    int blk = (w < 4) ? w : (11 - w);      // pair low/high row-blocks per SMSP
    int row = blk * 32 + lane;

    const float sc = 0.125f * 1.44269504089f;   // 1/sqrt(64) * log2(e)
    unsigned long long qv[32];
    const float4* qp = (const float4*)(g_q + ((size_t)b * TT + row) * HH);
#pragma unroll
    for (int i = 0; i < 16; i++) {
        float4 t = qp[i];
        qv[2 * i]     = pk2(t.x * sc, t.y * sc);
        qv[2 * i + 1] = pk2(t.z * sc, t.w * sc);
    }

    unsigned long long acc[32];
#pragma unroll
    for (int i = 0; i < 32; i++) acc[i] = 0ull;
    float m = -INFINITY, l = 0.f;

    __syncthreads();

    for (int jc = 0; jc <= row; jc += 16) {
        int rem = row - jc;
        float s[16];
#pragma unroll
        for (int jg = 0; jg < 16; jg += 4) {
            const float4* k0 = (const float4*)(ks + (jc + jg + 0) * HH);
            const float4* k1 = (const float4*)(ks + (jc + jg + 1) * HH);
            const float4* k2 = (const float4*)(ks + (jc + jg + 2) * HH);
            const float4* k3 = (const float4*)(ks + (jc + jg + 3) * HH);
            unsigned long long d0 = 0, d1 = 0, d2 = 0, d3 = 0;
#pragma unroll
            for (int i = 0; i < 16; i++) {
                float4 a0 = k0[i], a1 = k1[i], a2 = k2[i], a3 = k3[i];
                fma2(d0, qv[2 * i], pk2(a0.x, a0.y)); fma2(d0, qv[2 * i + 1], pk2(a0.z, a0.w));
                fma2(d1, qv[2 * i], pk2(a1.x, a1.y)); fma2(d1, qv[2 * i + 1], pk2(a1.z, a1.w));
                fma2(d2, qv[2 * i], pk2(a2.x, a2.y)); fma2(d2, qv[2 * i + 1], pk2(a2.z, a2.w));
                fma2(d3, qv[2 * i], pk2(a3.x, a3.y)); fma2(d3, qv[2 * i + 1], pk2(a3.z, a3.w));
            }
            float2 e0 = upk2(d0), e1 = upk2(d1), e2 = upk2(d2), e3 = upk2(d3);
            s[jg + 0] = e0.x + e0.y;
            s[jg + 1] = e1.x + e1.y;
            s[jg + 2] = e2.x + e2.y;
            s[jg + 3] = e3.x + e3.y;
        }
        float cmax = -INFINITY;
#pragma unroll
        for (int jj = 0; jj < 16; jj++) {
            s[jj] = (jj <= rem) ? s[jj] : -INFINITY;
            cmax = fmaxf(cmax, s[jj]);
        }
        float mnew = fmaxf(m, cmax);
        float corr = ex2f(m - mnew);
        m = mnew;
        l *= corr;
        unsigned long long c2 = pk2(corr, corr);
#pragma unroll
        for (int i = 0; i < 32; i++) acc[i] = mul2(acc[i], c2);
#pragma unroll
        for (int jj = 0; jj < 16; jj++) {
            float p = ex2f(s[jj] - m);      // masked: ex2(-inf) -> 0
            l += p;
            unsigned long long p2 = pk2(p, p);
            const float4* vr = (const float4*)(vs + (jc + jj) * HH);
#pragma unroll
            for (int i = 0; i < 16; i++) {
                float4 vv = vr[i];
                fma2(acc[2 * i],     p2, pk2(vv.x, vv.y));
                fma2(acc[2 * i + 1], p2, pk2(vv.z, vv.w));
            }
        }
    }

    float inv = 1.0f / l;
    unsigned long long i2 = pk2(inv, inv);

    __syncthreads();
    float4* s4 = (float4*)ks;
#pragma unroll
    for (int i = 0; i < 16; i++) {
        float2 a0 = upk2(mul2(acc[2 * i], i2));
        float2 a1 = upk2(mul2(acc[2 * i + 1], i2));
        s4[row * 17 + i] = make_float4(a0.x, a0.y, a1.x, a1.y);
    }
    __syncthreads();
    float4* ob = (float4*)(out + (size_t)b * TT * HH);
#pragma unroll 4
    for (int gi = tid; gi < TT * HH / 4; gi += 256) {
        ob[gi] = s4[(gi >> 4) * 17 + (gi & 15)];
    }
}

extern "C" void kernel_launch(void* const* d_in, const int* in_sizes, int n_in,
                              void* d_out, int out_size)
{
    (void)in_sizes; (void)n_in; (void)out_size;
    const float* x  = (const float*)d_in[0];
    const float* Wq = (const float*)d_in[1];
    const float* Wk = (const float*)d_in[2];
    const float* Wv = (const float*)d_in[3];
    float* out = (float*)d_out;

    const int qkv_smem = 2 * QS_STAGE;                        // 100 KB
    const int attn_smem = 2 * TT * HH * (int)sizeof(float);   // 128 KB
    cudaFuncSetAttribute(qkv_kernel, cudaFuncAttributeMaxDynamicSharedMemorySize, qkv_smem);
    cudaFuncSetAttribute(attn_kernel, cudaFuncAttributeMaxDynamicSharedMemorySize, attn_smem);

    wt_kernel<<<(3 * HH * EE + 255) / 256, 256>>>(Wq, Wk, Wv);
    qkv_kernel<<<(BB * TT) / 128, 256, qkv_smem>>>(x);
    attn_kernel<<<BB, 256, attn_smem>>>(out);
}

// round 5
// speedup vs baseline: 3.1050x; 1.5216x over previous
#include <cuda_runtime.h>
#include <cstdint>

#define BB 1024
#define TT 256
#define EE 384
#define HH 64

// Scratch (no-allocation rule: __device__ globals).
__device__ float g_q[BB * TT * HH];
__device__ float g_k[BB * TT * HH];   // stored tf32-rounded
__device__ float g_v[BB * TT * HH];   // stored tf32-rounded
// W fused+transposed+k-permuted+tf32-rounded: [mat][n][k_perm], row = m*64+n.
__device__ float g_wt[3 * HH * EE];

// ---------------------------------------------------------------------------
// helpers
// ---------------------------------------------------------------------------
__device__ __forceinline__ float ex2f(float x) {
    float y;
    asm("ex2.approx.ftz.f32 %0, %1;" : "=f"(y) : "f"(x));
    return y;
}
__device__ __forceinline__ uint32_t tf32r(float f) {
    uint32_t r;
    asm("cvt.rna.tf32.f32 %0, %1;" : "=r"(r) : "f"(f));
    return r;
}
// m16n8k8 tf32 mma (baseline PTX, works on compute_103).
__device__ __forceinline__ void mma8(float* d, const uint32_t* a, uint32_t b0, uint32_t b1) {
    asm("mma.sync.aligned.m16n8k8.row.col.f32.tf32.tf32.f32 "
        "{%0,%1,%2,%3}, {%4,%5,%6,%7}, {%8,%9}, {%0,%1,%2,%3};"
        : "+f"(d[0]), "+f"(d[1]), "+f"(d[2]), "+f"(d[3])
        : "r"(a[0]), "r"(a[1]), "r"(a[2]), "r"(a[3]), "r"(b0), "r"(b1));
}
__device__ __forceinline__ void cpa16(uint32_t dst, const void* src) {
    asm volatile("cp.async.cg.shared.global [%0], [%1], 16;" :: "r"(dst), "l"(src));
}
__device__ __forceinline__ uint32_t smem_u32(const void* p) {
    uint32_t a;
    asm("{ .reg .u64 t; cvta.to.shared.u64 t, %1; cvt.u32.u64 %0, t; }" : "=r"(a) : "l"(p));
    return a;
}
__device__ __forceinline__ float shflx(float v, int m) {
    return __shfl_xor_sync(0xffffffffu, v, m);
}

// ---------------------------------------------------------------------------
// Kernel 0: build g_wt. Row = m*64+n, col kp; within each 8-group, position p
// holds source k = base + (p>>1) + ((p&1)<<2) so the B fragment (b0 at k=c,
// b1 at k=c+4) is one aligned 8-byte LDS.64. Values tf32-rounded (rna).
// ---------------------------------------------------------------------------
__global__ void wt_kernel(const float* __restrict__ Wq, const float* __restrict__ Wk,
                          const float* __restrict__ Wv) {
    int idx = blockIdx.x * 256 + threadIdx.x;
    if (idx >= 3 * HH * EE) return;
    int m  = idx / (HH * EE);
    int n  = (idx / EE) & 63;
    int kp = idx % EE;
    int k  = (kp & ~7) + ((kp & 7) >> 1) + ((kp & 1) << 2);
    const float* W = (m == 0) ? Wq : (m == 1) ? Wk : Wv;
    uint32_t v = tf32r(W[k * HH + n]);
    g_wt[idx] = __uint_as_float(v);
}

// ---------------------------------------------------------------------------
// Kernel 1: QKV projection with mma.sync tf32 (unchanged from R4 except the
// epilogue tf32-rounds the k and v outputs so attn can feed smem bits to the
// tensor cores without per-load cvt).
// ---------------------------------------------------------------------------
#define QS_STAGE 51200
#define QS_WOFF  20480

__device__ __forceinline__ void qkv_load(uint32_t sbase, int stage, int chunk,
                                         const float* __restrict__ x, long long r0) {
    uint32_t xs = sbase + stage * QS_STAGE;
    uint32_t ws = xs + QS_WOFF;
    int tid = threadIdx.x;
#pragma unroll
    for (int i = 0; i < 4; i++) {                 // x: 128 rows x 32 f
        int idx = tid + i * 256;
        int row = idx >> 3, c16 = idx & 7;
        uint32_t doff = (uint32_t)(c16 * 16) ^ (uint32_t)((row & 4) << 2);
        cpa16(xs + row * 160 + doff, x + (r0 + row) * EE + chunk * 32 + c16 * 4);
    }
#pragma unroll
    for (int i = 0; i < 6; i++) {                 // W: 192 rows x 32 f
        int idx = tid + i * 256;
        int row = idx >> 3, c16 = idx & 7;
        cpa16(ws + row * 160 + c16 * 16, g_wt + row * EE + chunk * 32 + c16 * 4);
    }
}

__global__ void __launch_bounds__(256, 1) qkv_kernel(const float* __restrict__ x)
{
    extern __shared__ __align__(16) char smem[];
    uint32_t sbase = smem_u32(smem);
    int tid = threadIdx.x, wid = tid >> 5, lane = tid & 31;
    int g = lane >> 2, tig = lane & 3;
    int wm = wid >> 1, nh = wid & 1;
    int rb = wm * 32;
    long long r0 = (long long)blockIdx.x * 128;

    float acc[12][2][4];
#pragma unroll
    for (int nt = 0; nt < 12; nt++)
#pragma unroll
        for (int mt = 0; mt < 2; mt++)
#pragma unroll
            for (int i = 0; i < 4; i++) acc[nt][mt][i] = 0.f;

    qkv_load(sbase, 0, 0, x, r0);
    asm volatile("cp.async.commit_group;" ::: "memory");
    qkv_load(sbase, 1, 1, x, r0);
    asm volatile("cp.async.commit_group;" ::: "memory");

    for (int c = 0; c < 12; c++) {
        if (c < 11) asm volatile("cp.async.wait_group 1;" ::: "memory");
        else        asm volatile("cp.async.wait_group 0;" ::: "memory");
        __syncthreads();

        const float* xs = (const float*)(smem + (c & 1) * QS_STAGE);
        const float* ws = (const float*)(smem + (c & 1) * QS_STAGE + QS_WOFF);
#pragma unroll
        for (int ks = 0; ks < 4; ks++) {
            int kb = ks * 8;
            uint32_t A[2][4];
#pragma unroll
            for (int mt = 0; mt < 2; mt++) {
                int r_ = rb + mt * 16 + g;
                int sw = r_ & 4;                 // XOR swizzle bit
                A[mt][0] = tf32r(xs[r_ * 40 + ((kb + tig) ^ sw)]);
                A[mt][1] = tf32r(xs[(r_ + 8) * 40 + ((kb + tig) ^ sw)]);
                A[mt][2] = tf32r(xs[r_ * 40 + ((kb + tig + 4) ^ sw)]);
                A[mt][3] = tf32r(xs[(r_ + 8) * 40 + ((kb + tig + 4) ^ sw)]);
            }
#pragma unroll
            for (int nt = 0; nt < 12; nt++) {
                int brow = nh * 96 + nt * 8 + g;
                float2 bv = *(const float2*)&ws[brow * 40 + kb + 2 * tig];
                uint32_t b0 = __float_as_uint(bv.x), b1 = __float_as_uint(bv.y);
                mma8(acc[nt][0], A[0], b0, b1);
                mma8(acc[nt][1], A[1], b0, b1);
            }
        }
        __syncthreads();

        if (c + 2 < 12) {
            qkv_load(sbase, c & 1, c + 2, x, r0);
            asm volatile("cp.async.commit_group;" ::: "memory");
        }
    }

    // epilogue: q stays fp32; k and v are tf32-rounded for the attn mma feed.
    float* const outs[3] = { g_q, g_k, g_v };
#pragma unroll
    for (int nt = 0; nt < 12; nt++) {
        int gc = nh * 96 + nt * 8;
        int mat = gc >> 6;
        float* op = outs[mat] + (gc & 63) + 2 * tig;
#pragma unroll
        for (int mt = 0; mt < 2; mt++) {
            long long row0 = r0 + rb + mt * 16 + g;
            float v0 = acc[nt][mt][0], v1 = acc[nt][mt][1];
            float v2 = acc[nt][mt][2], v3 = acc[nt][mt][3];
            if (mat != 0) {
                v0 = __uint_as_float(tf32r(v0)); v1 = __uint_as_float(tf32r(v1));
                v2 = __uint_as_float(tf32r(v2)); v3 = __uint_as_float(tf32r(v3));
            }
            *(float2*)(op + row0 * HH) = make_float2(v0, v1);
            *(float2*)(op + (row0 + 8) * HH) = make_float2(v2, v3);
        }
    }
}

// ---------------------------------------------------------------------------
// Kernel 2: flash attention with mma.sync tf32.
// 1 CTA/batch, 8 warps. Warp w owns 16-row m-tiles {w, 15-w} -> exactly 5
// key-chunks of 64 per warp (balanced causal work).
// smem: ks [256][68], vs [256][68] (stride 68: K b-frags conflict-free,
// V b-frags 2-way worst case), per-warp P tile [16][68].
// ---------------------------------------------------------------------------
#define KST 68
#define ATTN_SMEM ((2 * 256 * KST + 8 * 16 * KST) * 4)

__global__ void __launch_bounds__(256, 1) attn_kernel(float* __restrict__ out)
{
    extern __shared__ __align__(16) float sm[];
    float* ks = sm;                          // [256][68]
    float* vs = sm + 256 * KST;              // [256][68]
    int b = blockIdx.x;
    int tid = threadIdx.x, w = tid >> 5, lane = tid & 31;
    int g = lane >> 2, tig = lane & 3;
    float* pw = sm + 2 * 256 * KST + w * (16 * KST);

    // cooperative K/V load (values already tf32-rounded in global)
    {
        uint32_t ksu = smem_u32(ks);
        const float* kg = g_k + (size_t)b * TT * HH;
        const float* vg = g_v + (size_t)b * TT * HH;
#pragma unroll
        for (int i = 0; i < 16; i++) {
            int idx = tid + i * 256;          // 0..4095 float4s
            int key = idx >> 4, h4 = idx & 15;
            cpa16(ksu + (uint32_t)(key * KST + h4 * 4) * 4, kg + key * 64 + h4 * 4);
            cpa16(ksu + (uint32_t)(256 * KST + key * KST + h4 * 4) * 4, vg + key * 64 + h4 * 4);
        }
        asm volatile("cp.async.commit_group;" ::: "memory");
    }

    // Q fragments for both m-tiles, pre-scaled by 1/sqrt(H)*log2(e), tf32.
    const float scl = 0.125f * 1.44269504089f;
    int bs[2] = { w, 15 - w };
    uint32_t qf[2][8][4];
    const float* qg = g_q + (size_t)b * TT * HH;
#pragma unroll
    for (int t = 0; t < 2; t++) {
        int m0 = bs[t] * 16;
#pragma unroll
        for (int kc = 0; kc < 8; kc++) {
            qf[t][kc][0] = tf32r(scl * qg[(m0 + g) * 64 + kc * 8 + tig]);
            qf[t][kc][1] = tf32r(scl * qg[(m0 + 8 + g) * 64 + kc * 8 + tig]);
            qf[t][kc][2] = tf32r(scl * qg[(m0 + g) * 64 + kc * 8 + tig + 4]);
            qf[t][kc][3] = tf32r(scl * qg[(m0 + 8 + g) * 64 + kc * 8 + tig + 4]);
        }
    }

    asm volatile("cp.async.wait_group 0;" ::: "memory");
    __syncthreads();

#pragma unroll
    for (int t = 0; t < 2; t++) {
        int bb = bs[t], m0 = bb * 16;
        int nch = (bb + 4) >> 2;             // ceil((bb+1)/4)
        float o[8][4];
#pragma unroll
        for (int nt = 0; nt < 8; nt++)
#pragma unroll
            for (int e = 0; e < 4; e++) o[nt][e] = 0.f;
        float mr0 = -INFINITY, mr1 = -INFINITY, l0 = 0.f, l1 = 0.f;

        for (int ci = 0; ci < nch; ci++) {
            int kc0 = ci * 64;
            // ---- QK^T: S[16][64] ----
            float s[8][4];
#pragma unroll
            for (int nt = 0; nt < 8; nt++)
#pragma unroll
                for (int e = 0; e < 4; e++) s[nt][e] = 0.f;
#pragma unroll
            for (int kc = 0; kc < 8; kc++) {
#pragma unroll
                for (int nt = 0; nt < 8; nt++) {
                    const float* kr = ks + (kc0 + nt * 8 + g) * KST + kc * 8;
                    uint32_t b0 = __float_as_uint(kr[tig]);
                    uint32_t b1 = __float_as_uint(kr[tig + 4]);
                    mma8(s[nt], qf[t][kc], b0, b1);
                }
            }
            // ---- causal mask (warp-uniform branch) ----
            if (kc0 + 63 > m0) {
                int r0_ = m0 + g, r1_ = m0 + 8 + g;
#pragma unroll
                for (int nt = 0; nt < 8; nt++) {
                    int k0_ = kc0 + nt * 8 + 2 * tig;
                    s[nt][0] = (k0_     <= r0_) ? s[nt][0] : -INFINITY;
                    s[nt][1] = (k0_ + 1 <= r0_) ? s[nt][1] : -INFINITY;
                    s[nt][2] = (k0_     <= r1_) ? s[nt][2] : -INFINITY;
                    s[nt][3] = (k0_ + 1 <= r1_) ? s[nt][3] : -INFINITY;
                }
            }
            // ---- online softmax (base-2) ----
            float mx0 = s[0][0], mx1 = s[0][2];
#pragma unroll
            for (int nt = 0; nt < 8; nt++) {
                mx0 = fmaxf(mx0, fmaxf(s[nt][0], s[nt][1]));
                mx1 = fmaxf(mx1, fmaxf(s[nt][2], s[nt][3]));
            }
            mx0 = fmaxf(mx0, shflx(mx0, 1)); mx0 = fmaxf(mx0, shflx(mx0, 2));
            mx1 = fmaxf(mx1, shflx(mx1, 1)); mx1 = fmaxf(mx1, shflx(mx1, 2));
            float mn0 = fmaxf(mr0, mx0), mn1 = fmaxf(mr1, mx1);
            float c0 = ex2f(mr0 - mn0), c1 = ex2f(mr1 - mn1);
            mr0 = mn0; mr1 = mn1;
            float p0 = 0.f, p1 = 0.f;
#pragma unroll
            for (int nt = 0; nt < 8; nt++) {
                s[nt][0] = ex2f(s[nt][0] - mr0);
                s[nt][1] = ex2f(s[nt][1] - mr0);
                s[nt][2] = ex2f(s[nt][2] - mr1);
                s[nt][3] = ex2f(s[nt][3] - mr1);
                p0 += s[nt][0] + s[nt][1];
                p1 += s[nt][2] + s[nt][3];
            }
            p0 += shflx(p0, 1); p0 += shflx(p0, 2);
            p1 += shflx(p1, 1); p1 += shflx(p1, 2);
            l0 = l0 * c0 + p0;
            l1 = l1 * c1 + p1;
            // rescale O
#pragma unroll
            for (int nt = 0; nt < 8; nt++) {
                o[nt][0] *= c0; o[nt][1] *= c0;
                o[nt][2] *= c1; o[nt][3] *= c1;
            }
            // ---- stage P (tf32-rounded) ----
            __syncwarp();
#pragma unroll
            for (int nt = 0; nt < 8; nt++) {
                int cb = nt * 8 + 2 * tig;
                *(float2*)&pw[g * KST + cb] =
                    make_float2(__uint_as_float(tf32r(s[nt][0])), __uint_as_float(tf32r(s[nt][1])));
                *(float2*)&pw[(8 + g) * KST + cb] =
                    make_float2(__uint_as_float(tf32r(s[nt][2])), __uint_as_float(tf32r(s[nt][3])));
            }
            __syncwarp();
            // ---- P @ V ----
#pragma unroll
            for (int kc2 = 0; kc2 < 8; kc2++) {
                uint32_t pa[4];
                pa[0] = __float_as_uint(pw[g * KST + kc2 * 8 + tig]);
                pa[1] = __float_as_uint(pw[(8 + g) * KST + kc2 * 8 + tig]);
                pa[2] = __float_as_uint(pw[g * KST + kc2 * 8 + tig + 4]);
                pa[3] = __float_as_uint(pw[(8 + g) * KST + kc2 * 8 + tig + 4]);
                const float* v0p = vs + (kc0 + kc2 * 8 + tig) * KST;
                const float* v1p = vs + (kc0 + kc2 * 8 + tig + 4) * KST;
#pragma unroll
                for (int nt2 = 0; nt2 < 8; nt2++) {
                    uint32_t b0 = __float_as_uint(v0p[nt2 * 8 + g]);
                    uint32_t b1 = __float_as_uint(v1p[nt2 * 8 + g]);
                    mma8(o[nt2], pa, b0, b1);
                }
            }
        }

        // ---- normalize + store ----
        float inv0 = 1.0f / l0, inv1 = 1.0f / l1;
        float* ob = out + ((size_t)b * TT + m0) * HH;
#pragma unroll
        for (int nt = 0; nt < 8; nt++) {
            int cb = nt * 8 + 2 * tig;
            *(float2*)(ob + g * 64 + cb) = make_float2(o[nt][0] * inv0, o[nt][1] * inv0);
            *(float2*)(ob + (8 + g) * 64 + cb) = make_float2(o[nt][2] * inv1, o[nt][3] * inv1);
        }
    }
}

extern "C" void kernel_launch(void* const* d_in, const int* in_sizes, int n_in,
                              void* d_out, int out_size)
{
    (void)in_sizes; (void)n_in; (void)out_size;
    const float* x  = (const float*)d_in[0];
    const float* Wq = (const float*)d_in[1];
    const float* Wk = (const float*)d_in[2];
    const float* Wv = (const float*)d_in[3];
    float* out = (float*)d_out;

    const int qkv_smem = 2 * QS_STAGE;                        // 100 KB
    cudaFuncSetAttribute(qkv_kernel, cudaFuncAttributeMaxDynamicSharedMemorySize, qkv_smem);
    cudaFuncSetAttribute(attn_kernel, cudaFuncAttributeMaxDynamicSharedMemorySize, ATTN_SMEM);

    wt_kernel<<<(3 * HH * EE + 255) / 256, 256>>>(Wq, Wk, Wv);
    qkv_kernel<<<(BB * TT) / 128, 256, qkv_smem>>>(x);
    attn_kernel<<<BB, 256, ATTN_SMEM>>>(out);
}